// round 15
// baseline (speedup 1.0000x reference)
#include <cuda_runtime.h>
#include <cstdint>

// Problem constants (fixed by the dataset)
#define GROUPS 8
#define RANK  3
#define SCALING 2.0f                     // 6.0 / 3.0
#define EPS 1e-6f

#define N4    16777216                   // total float4 (fits int32)
#define V_PER_ROW 1024                   // float4 per d-row (4096/4)
#define V_GROUP_SHIFT 7                  // 128 float4 per group

#define TPB 256
// Each block: 2 rows x 256 cols of float4 -> 512 float4.
// Row pairing keeps the group constant per thread (group = col>>7).
#define ROWS  16384                      // N4 / V_PER_ROW
#define NBLOCKS ((ROWS / 2) * (V_PER_ROW / TPB))   // 8192 * 4 = 32768

__global__ __launch_bounds__(TPB, 7)
void nora_rational_kernel(
    const float4* __restrict__ x,
    float4* __restrict__ out,
    const float* __restrict__ base_num,   // [G,6]
    const float* __restrict__ base_den,   // [G,4]
    const float* __restrict__ lA_num,     // [R,6]
    const float* __restrict__ lB_num,     // [G,R]
    const float* __restrict__ lA_den,     // [R,4]
    const float* __restrict__ lB_den)     // [G,R]
{
    // Packed coefficients: per group 3 float4 words:
    //   c0 = {a0, a1, a2, a3}
    //   c1 = {a4, a5, b0, b1}
    //   c2 = {b2, b3, 0, 0}
    __shared__ float4 s_coef[GROUPS][3];

    const int t = threadIdx.x;

    // Fuse LoRA into coefficients (80 scalar results, first 80 threads),
    // scattered into the packed layout.
    float* s_flat = (float*)s_coef;      // group g occupies s_flat[g*12 .. g*12+11]
    if (t < GROUPS * 6) {
        int g = t / 6, k = t % 6;
        float acc = base_num[t];
        #pragma unroll
        for (int r = 0; r < RANK; ++r)
            acc = fmaf(lB_num[g * RANK + r] * SCALING, lA_num[r * 6 + k], acc);
        s_flat[g * 12 + k] = acc;                    // a_k -> slots 0..5
    } else if (t < GROUPS * 6 + GROUPS * 4) {
        int u = t - GROUPS * 6;
        int g = u / 4, k = u % 4;
        float acc = base_den[u];
        #pragma unroll
        for (int r = 0; r < RANK; ++r)
            acc = fmaf(lB_den[g * RANK + r] * SCALING, lA_den[r * 4 + k], acc);
        s_flat[g * 12 + 6 + k] = acc + EPS;          // b_k -> slots 6..9
    } else if (t < GROUPS * 6 + GROUPS * 4 + 2 * GROUPS) {
        int u = t - GROUPS * 10;
        s_flat[(u / 2) * 12 + 10 + (u & 1)] = 0.0f;  // padding slots 10,11
    }
    __syncthreads();

    // Block decomposition: row pair + column chunk.
    const int b  = blockIdx.x;
    const int rp = b >> 2;                 // row pair index (0..8191)
    const int cc = b & 3;                  // column chunk (0..3)
    const int col = cc * TPB + t;          // 0..1023, warp-contiguous
    const int g   = col >> V_GROUP_SHIFT;  // constant for BOTH elements

    const int i0 = rp * (2 * V_PER_ROW) + col;
    const int i1 = i0 + V_PER_ROW;

    // Front-batched streaming loads (evict-first; single-touch data).
    float4 xv0 = __ldcs(&x[i0]);
    float4 xv1 = __ldcs(&x[i1]);

    // Coefficients: 3 x LDS.128, warp-uniform broadcast (conflict-free).
    const float4 c0 = s_coef[g][0];
    const float4 c1 = s_coef[g][1];
    const float4 c2 = s_coef[g][2];

    const float a0 = c0.x, a1 = c0.y, a2 = c0.z, a3 = c0.w;
    const float a4 = c1.x, a5 = c1.y, b0 = c1.z, b1 = c1.w;
    const float b2 = c2.x, b3 = c2.y;

    #pragma unroll
    for (int j = 0; j < 2; ++j) {
        float4 v = (j == 0) ? xv0 : xv1;
        float4 ov;
        #pragma unroll
        for (int lane = 0; lane < 4; ++lane) {
            float xx = (lane == 0) ? v.x : (lane == 1) ? v.y : (lane == 2) ? v.z : v.w;
            // P(x) = a0 + a1 x + ... + a5 x^5  (Horner)
            float p = fmaf(a5, xx, a4);
            p = fmaf(p, xx, a3);
            p = fmaf(p, xx, a2);
            p = fmaf(p, xx, a1);
            p = fmaf(p, xx, a0);
            // Q(x) = 1 + |b0 x + b1 x^2 + b2 x^3 + b3 x^4|
            float z = fmaf(b3, xx, b2);
            z = fmaf(z, xx, b1);
            z = fmaf(z, xx, b0);
            float q = 1.0f + fabsf(z * xx);
            float r = __fdividef(p, q);
            if (lane == 0) ov.x = r; else if (lane == 1) ov.y = r;
            else if (lane == 2) ov.z = r; else ov.w = r;
        }
        __stcs(&out[(j == 0) ? i0 : i1], ov);
    }
}

extern "C" void kernel_launch(void* const* d_in, const int* in_sizes, int n_in,
                              void* d_out, int out_size)
{
    const float4* x  = (const float4*)d_in[0];
    const float* bn  = (const float*)d_in[1];
    const float* bd  = (const float*)d_in[2];
    const float* lAn = (const float*)d_in[3];
    const float* lBn = (const float*)d_in[4];
    const float* lAd = (const float*)d_in[5];
    const float* lBd = (const float*)d_in[6];

    float4* out = (float4*)d_out;

    nora_rational_kernel<<<NBLOCKS, TPB>>>(
        x, out, bn, bd, lAn, lBn, lAd, lBd);
}

// round 17
// speedup vs baseline: 1.0004x; 1.0004x over previous
#include <cuda_runtime.h>
#include <cstdint>

// Problem constants (fixed by the dataset)
#define GROUPS 8
#define RANK  3
#define SCALING 2.0f                     // 6.0 / 3.0
#define EPS 1e-6f

#define N4    16777216                   // total float4 (fits int32)
#define V_PER_ROW 1024                   // float4 per d-row (4096/4)
#define V_GROUP_SHIFT 7                  // 128 float4 per group

#define TPB 256
// Each block: 2 rows x 256 cols of float4 -> 512 float4.
// Row pairing keeps the group constant per thread (group = col>>7).
#define ROWS  16384                      // N4 / V_PER_ROW
#define NBLOCKS ((ROWS / 2) * (V_PER_ROW / TPB))   // 8192 * 4 = 32768

__global__ __launch_bounds__(TPB, 7)
void nora_rational_kernel(
    const float4* __restrict__ x,
    float4* __restrict__ out,
    const float* __restrict__ base_num,   // [G,6]
    const float* __restrict__ base_den,   // [G,4]
    const float* __restrict__ lA_num,     // [R,6]
    const float* __restrict__ lB_num,     // [G,R]
    const float* __restrict__ lA_den,     // [R,4]
    const float* __restrict__ lB_den)     // [G,R]
{
    // Packed coefficients: per group 3 float4 words:
    //   c0 = {a0, a1, a2, a3}
    //   c1 = {a4, a5, b0, b1}
    //   c2 = {b2, b3, 0, 0}
    __shared__ float4 s_coef[GROUPS][3];

    const int t = threadIdx.x;

    // Fuse LoRA into coefficients (80 scalar results, first 80 threads),
    // scattered into the packed layout.
    float* s_flat = (float*)s_coef;      // group g occupies s_flat[g*12 .. g*12+11]
    if (t < GROUPS * 6) {
        int g = t / 6, k = t % 6;
        float acc = base_num[t];
        #pragma unroll
        for (int r = 0; r < RANK; ++r)
            acc = fmaf(lB_num[g * RANK + r] * SCALING, lA_num[r * 6 + k], acc);
        s_flat[g * 12 + k] = acc;                    // a_k -> slots 0..5
    } else if (t < GROUPS * 6 + GROUPS * 4) {
        int u = t - GROUPS * 6;
        int g = u / 4, k = u % 4;
        float acc = base_den[u];
        #pragma unroll
        for (int r = 0; r < RANK; ++r)
            acc = fmaf(lB_den[g * RANK + r] * SCALING, lA_den[r * 4 + k], acc);
        s_flat[g * 12 + 6 + k] = acc + EPS;          // b_k -> slots 6..9
    } else if (t < GROUPS * 6 + GROUPS * 4 + 2 * GROUPS) {
        int u = t - GROUPS * 10;
        s_flat[(u / 2) * 12 + 10 + (u & 1)] = 0.0f;  // padding slots 10,11
    }
    __syncthreads();

    // Block decomposition: row pair + column chunk.
    const int b  = blockIdx.x;
    const int rp = b >> 2;                 // row pair index (0..8191)
    const int cc = b & 3;                  // column chunk (0..3)
    const int col = cc * TPB + t;          // 0..1023, warp-contiguous
    const int g   = col >> V_GROUP_SHIFT;  // constant for BOTH elements

    const int i0 = rp * (2 * V_PER_ROW) + col;
    const int i1 = i0 + V_PER_ROW;

    // Front-batched streaming loads (evict-first; single-touch data).
    float4 xv0 = __ldcs(&x[i0]);
    float4 xv1 = __ldcs(&x[i1]);

    // Coefficients: 3 x LDS.128, warp-uniform broadcast (conflict-free).
    const float4 c0 = s_coef[g][0];
    const float4 c1 = s_coef[g][1];
    const float4 c2 = s_coef[g][2];

    const float a0 = c0.x, a1 = c0.y, a2 = c0.z, a3 = c0.w;
    const float a4 = c1.x, a5 = c1.y, b0 = c1.z, b1 = c1.w;
    const float b2 = c2.x, b3 = c2.y;

    #pragma unroll
    for (int j = 0; j < 2; ++j) {
        float4 v = (j == 0) ? xv0 : xv1;
        float4 ov;
        #pragma unroll
        for (int lane = 0; lane < 4; ++lane) {
            float xx = (lane == 0) ? v.x : (lane == 1) ? v.y : (lane == 2) ? v.z : v.w;
            // P(x) = a0 + a1 x + ... + a5 x^5  (Horner)
            float p = fmaf(a5, xx, a4);
            p = fmaf(p, xx, a3);
            p = fmaf(p, xx, a2);
            p = fmaf(p, xx, a1);
            p = fmaf(p, xx, a0);
            // Q(x) = 1 + |b0 x + b1 x^2 + b2 x^3 + b3 x^4|
            float z = fmaf(b3, xx, b2);
            z = fmaf(z, xx, b1);
            z = fmaf(z, xx, b0);
            float q = 1.0f + fabsf(z * xx);
            float r = __fdividef(p, q);
            if (lane == 0) ov.x = r; else if (lane == 1) ov.y = r;
            else if (lane == 2) ov.z = r; else ov.w = r;
        }
        __stcs(&out[(j == 0) ? i0 : i1], ov);
    }
}

extern "C" void kernel_launch(void* const* d_in, const int* in_sizes, int n_in,
                              void* d_out, int out_size)
{
    const float4* x  = (const float4*)d_in[0];
    const float* bn  = (const float*)d_in[1];
    const float* bd  = (const float*)d_in[2];
    const float* lAn = (const float*)d_in[3];
    const float* lBn = (const float*)d_in[4];
    const float* lAd = (const float*)d_in[5];
    const float* lBd = (const float*)d_in[6];

    float4* out = (float4*)d_out;

    nora_rational_kernel<<<NBLOCKS, TPB>>>(
        x, out, bn, bd, lAn, lBn, lAd, lBd);
}